// round 10
// baseline (speedup 1.0000x reference)
#include <cuda_runtime.h>
#include <cuda_bf16.h>

#define LN 5
#define CN 16
#define HN 256
#define WN 256
#define HW (HN*WN)
#define BN_EPS 1e-5f
#define INV_RATIO 1.25f   /* 1 / (0.4 * 2) */

typedef unsigned long long u64;

// ---- packed f32x2 helpers (sm_103a dual-FP32 pipe; ptxas never auto-emits) ----
union F2u { u64 u; float2 f; };

__device__ __forceinline__ u64 ffma2(u64 a, u64 b, u64 c) {
    u64 d;
    asm("fma.rn.f32x2 %0, %1, %2, %3;" : "=l"(d) : "l"(a), "l"(b), "l"(c));
    return d;
}
__device__ __forceinline__ u64 fmul2(u64 a, u64 b) {
    u64 d;
    asm("mul.rn.f32x2 %0, %1, %2;" : "=l"(d) : "l"(a), "l"(b));
    return d;
}
__device__ __forceinline__ u64 pack2(float lo, float hi) {
    F2u r; r.f.x = lo; r.f.y = hi; return r.u;
}
__device__ __forceinline__ u64 ldc2(const float2& p) {
    F2u r; r.f = p; return r.u;
}
__device__ __forceinline__ float hadd2(u64 a) {
    F2u r; r.u = a; return r.f.x + r.f.y;
}

// All loop-invariant parameters live in the constant bank -> LDCU/uniform port.
// Rows are 8-byte aligned so weight pairs load as single LDCU.64.
struct alignas(16) Consts {
    float minv[25][6];     // 600 B
    float w1n[16][16];     // layer1, nb half (BN-folded)
    float w1e[16][16];     // layer1, ego half (BN-folded)
    float b1[16];
    float w2[8][16];  float b2[8];
    float w3[4][8];   float b3[4];
    float w4[4];      float b4;  float pad;   // pad keeps wm rows 8B-aligned
    float wm[16][16]; float bm[16];
};

__constant__ Consts cc;      // read by the main kernel
__device__   Consts g_fold;  // staging: written by fold kernel, memcpy'd to cc

// ---- prologue: BN-fold + affine inversion into the staging struct ----
__global__ __launch_bounds__(256) void fold_kernel(
    const float* __restrict__ ptm,
    const float* __restrict__ w1, const float* __restrict__ b1,
    const float* __restrict__ g1, const float* __restrict__ be1,
    const float* __restrict__ rm1, const float* __restrict__ rv1,
    const float* __restrict__ w2, const float* __restrict__ b2,
    const float* __restrict__ g2, const float* __restrict__ be2,
    const float* __restrict__ rm2, const float* __restrict__ rv2,
    const float* __restrict__ w3, const float* __restrict__ b3,
    const float* __restrict__ g3, const float* __restrict__ be3,
    const float* __restrict__ rm3, const float* __restrict__ rv3,
    const float* __restrict__ w4, const float* __restrict__ b4,
    const float* __restrict__ wm, const float* __restrict__ bm)
{
    const int tid = threadIdx.x;

    for (int idx = tid; idx < 16*32; idx += blockDim.x) {
        int o = idx >> 5, c = idx & 31;
        float v = w1[idx] * (g1[o] * rsqrtf(rv1[o] + BN_EPS));
        if (c < 16) g_fold.w1n[o][c]      = v;
        else        g_fold.w1e[o][c - 16] = v;
    }
    for (int idx = tid; idx < 8*16; idx += blockDim.x) {
        int o = idx >> 4;
        g_fold.w2[o][idx & 15] = w2[idx] * (g2[o] * rsqrtf(rv2[o] + BN_EPS));
    }
    for (int idx = tid; idx < 4*8; idx += blockDim.x) {
        int o = idx >> 3;
        g_fold.w3[o][idx & 7] = w3[idx] * (g3[o] * rsqrtf(rv3[o] + BN_EPS));
    }
    for (int idx = tid; idx < 16*16; idx += blockDim.x)
        g_fold.wm[idx >> 4][idx & 15] = wm[idx];

    if (tid < 16) {
        float sc = g1[tid] * rsqrtf(rv1[tid] + BN_EPS);
        g_fold.b1[tid] = (b1[tid] - rm1[tid]) * sc + be1[tid];
        g_fold.bm[tid] = bm[tid];
    }
    if (tid < 8) {
        float sc = g2[tid] * rsqrtf(rv2[tid] + BN_EPS);
        g_fold.b2[tid] = (b2[tid] - rm2[tid]) * sc + be2[tid];
    }
    if (tid < 4) {
        float sc = g3[tid] * rsqrtf(rv3[tid] + BN_EPS);
        g_fold.b3[tid] = (b3[tid] - rm3[tid]) * sc + be3[tid];
        g_fold.w4[tid] = w4[tid];
    }
    if (tid == 0) g_fold.b4 = b4[0];

    // analytic inverse of [[a,b,tx],[c,d,ty],[0,0,1]] for all 25 (j,i) pairs
    if (tid < 25) {
        const float* m = ptm + tid * 16;
        float a = m[0], b = m[1], tx = m[3] * INV_RATIO;
        float c = m[4], d = m[5], ty = m[7] * INV_RATIO;
        float inv = 1.0f / (a*d - b*c);
        g_fold.minv[tid][0] =  d * inv;
        g_fold.minv[tid][1] = -b * inv;
        g_fold.minv[tid][2] = (b*ty - d*tx) * inv;
        g_fold.minv[tid][3] = -c * inv;
        g_fold.minv[tid][4] =  a * inv;
        g_fold.minv[tid][5] = (c*tx - a*ty) * inv;
    }
}

// ---- main fused kernel: one thread = one (i, h, w) output pixel ----
__global__ __launch_bounds__(256, 3) void disco_fused_kernel(
    const float* __restrict__ x,     // [L,C,H,W]
    float* __restrict__ out)         // [L,C,H,W]
{
    const int gid = blockIdx.x * blockDim.x + threadIdx.x;
    const int i   = gid / HW;
    const int pix = gid - i * HW;
    const int h   = pix >> 8;
    const int w   = pix & 255;
    const float fw = (float)w, fh = (float)h;

    // ego channels -> j-invariant half of layer 1 (packed dot products)
    float egoPart[16];
    {
        u64 egop[8];
        const float* xi = x + (size_t)i * CN * HW + pix;
        #pragma unroll
        for (int p = 0; p < 8; p++)
            egop[p] = pack2(__ldg(xi + (2*p) * HW), __ldg(xi + (2*p+1) * HW));
        #pragma unroll
        for (int o = 0; o < 16; o++) {
            const float2* wr = reinterpret_cast<const float2*>(cc.w1e[o]);
            u64 a = pack2(cc.b1[o], 0.0f);
            #pragma unroll
            for (int p = 0; p < 8; p++) a = ffma2(ldc2(wr[p]), egop[p], a);
            egoPart[o] = hadd2(a);
        }
    }

    // softmax without max-tracking: logits are ReLU'd (>=0, small) -> no overflow.
    float ssum = 0.0f;
    u64 accp[8];
    #pragma unroll
    for (int p = 0; p < 8; p++) accp[p] = pack2(0.0f, 0.0f);

    #pragma unroll 1
    for (int j = 0; j < LN; j++) {
        // source coords via inv(T[j][i])
        const int mi = j * 5 + i;
        float sx = cc.minv[mi][0]*fw + cc.minv[mi][1]*fh + cc.minv[mi][2];
        float sy = cc.minv[mi][3]*fw + cc.minv[mi][4]*fh + cc.minv[mi][5];
        float x0f = floorf(sx), y0f = floorf(sy);
        float wx = sx - x0f,    wy = sy - y0f;
        bool vx0 = (x0f >=  0.0f) && (x0f <= 255.0f);
        bool vx1 = (x0f >= -1.0f) && (x0f <= 254.0f);
        bool vy0 = (y0f >=  0.0f) && (y0f <= 255.0f);
        bool vy1 = (y0f >= -1.0f) && (y0f <= 254.0f);
        float w00 = (vx0 && vy0) ? (1.0f - wx) * (1.0f - wy) : 0.0f;
        float w01 = (vx1 && vy0) ? wx * (1.0f - wy) : 0.0f;
        float w10 = (vx0 && vy1) ? (1.0f - wx) * wy : 0.0f;
        float w11 = (vx1 && vy1) ? wx * wy : 0.0f;
        int ix0 = (int)x0f, iy0 = (int)y0f;
        int cx0 = min(max(ix0,     0), 255);
        int cx1 = min(max(ix0 + 1, 0), 255);
        int cy0 = min(max(iy0,     0), 255);
        int cy1 = min(max(iy0 + 1, 0), 255);
        int o00 = cy0 * WN + cx0, o01 = cy0 * WN + cx1;
        int o10 = cy1 * WN + cx0, o11 = cy1 * WN + cx1;

        // bilinear sample 16 channels, packed in channel pairs
        u64 nbp[8];
        {
            const float* xj = x + (size_t)j * CN * HW;
            u64 W00 = pack2(w00, w00), W01 = pack2(w01, w01);
            u64 W10 = pack2(w10, w10), W11 = pack2(w11, w11);
            #pragma unroll
            for (int p = 0; p < 8; p++) {
                const float* c0 = xj + (2*p)   * HW;
                const float* c1 = xj + (2*p+1) * HW;
                u64 a = fmul2(W00, pack2(__ldg(c0 + o00), __ldg(c1 + o00)));
                a = ffma2(W01, pack2(__ldg(c0 + o01), __ldg(c1 + o01)), a);
                a = ffma2(W10, pack2(__ldg(c0 + o10), __ldg(c1 + o10)), a);
                a = ffma2(W11, pack2(__ldg(c0 + o11), __ldg(c1 + o11)), a);
                nbp[p] = a;
            }
        }

        // MLP 32->16->8->4->1 (ego half precomputed), packed dot products
        u64 h1p[8];
        #pragma unroll
        for (int o2 = 0; o2 < 8; o2++) {
            const float2* wr0 = reinterpret_cast<const float2*>(cc.w1n[2*o2]);
            const float2* wr1 = reinterpret_cast<const float2*>(cc.w1n[2*o2+1]);
            u64 a0 = pack2(egoPart[2*o2],   0.0f);
            u64 a1 = pack2(egoPart[2*o2+1], 0.0f);
            #pragma unroll
            for (int p = 0; p < 8; p++) {
                a0 = ffma2(ldc2(wr0[p]), nbp[p], a0);
                a1 = ffma2(ldc2(wr1[p]), nbp[p], a1);
            }
            h1p[o2] = pack2(fmaxf(hadd2(a0), 0.0f), fmaxf(hadd2(a1), 0.0f));
        }
        u64 h2p[4];
        #pragma unroll
        for (int o2 = 0; o2 < 4; o2++) {
            const float2* wr0 = reinterpret_cast<const float2*>(cc.w2[2*o2]);
            const float2* wr1 = reinterpret_cast<const float2*>(cc.w2[2*o2+1]);
            u64 a0 = pack2(cc.b2[2*o2],   0.0f);
            u64 a1 = pack2(cc.b2[2*o2+1], 0.0f);
            #pragma unroll
            for (int p = 0; p < 8; p++) {
                a0 = ffma2(ldc2(wr0[p]), h1p[p], a0);
                a1 = ffma2(ldc2(wr1[p]), h1p[p], a1);
            }
            h2p[o2] = pack2(fmaxf(hadd2(a0), 0.0f), fmaxf(hadd2(a1), 0.0f));
        }
        u64 h3p[2];
        #pragma unroll
        for (int o2 = 0; o2 < 2; o2++) {
            const float2* wr0 = reinterpret_cast<const float2*>(cc.w3[2*o2]);
            const float2* wr1 = reinterpret_cast<const float2*>(cc.w3[2*o2+1]);
            u64 a0 = pack2(cc.b3[2*o2],   0.0f);
            u64 a1 = pack2(cc.b3[2*o2+1], 0.0f);
            #pragma unroll
            for (int p = 0; p < 4; p++) {
                a0 = ffma2(ldc2(wr0[p]), h2p[p], a0);
                a1 = ffma2(ldc2(wr1[p]), h2p[p], a1);
            }
            h3p[o2] = pack2(fmaxf(hadd2(a0), 0.0f), fmaxf(hadd2(a1), 0.0f));
        }
        const float2* w4p = reinterpret_cast<const float2*>(cc.w4);
        u64 al = pack2(cc.b4, 0.0f);
        al = ffma2(ldc2(w4p[0]), h3p[0], al);
        al = ffma2(ldc2(w4p[1]), h3p[1], al);
        float logit = fmaxf(hadd2(al), 0.0f);

        // un-normalized softmax accumulate
        float e = __expf(logit);
        ssum += e;
        u64 E = pack2(e, e);
        #pragma unroll
        for (int p = 0; p < 8; p++) accp[p] = ffma2(E, nbp[p], accp[p]);
    }

    // out = (wm @ acc) * rinv + bm
    float rinv = 1.0f / ssum;
    float* op = out + (size_t)i * CN * HW + pix;
    #pragma unroll
    for (int o = 0; o < 16; o++) {
        const float2* wr = reinterpret_cast<const float2*>(cc.wm[o]);
        u64 a = pack2(0.0f, 0.0f);
        #pragma unroll
        for (int p = 0; p < 8; p++) a = ffma2(ldc2(wr[p]), accp[p], a);
        op[o * HW] = hadd2(a) * rinv + cc.bm[o];
    }
}

extern "C" void kernel_launch(void* const* d_in, const int* in_sizes, int n_in,
                              void* d_out, int out_size) {
    (void)in_sizes; (void)n_in; (void)out_size;
    // metadata order: x, record_len, pairwise_t_matrix,
    // w1,b1,g1,be1,rm1,rv1, w2,b2,g2,be2,rm2,rv2, w3,b3,g3,be3,rm3,rv3, w4,b4, wm,bm
    const float* x   = (const float*)d_in[0];
    const float* ptm = (const float*)d_in[2];

    fold_kernel<<<1, 256>>>(
        ptm,
        (const float*)d_in[3],  (const float*)d_in[4],
        (const float*)d_in[5],  (const float*)d_in[6],
        (const float*)d_in[7],  (const float*)d_in[8],
        (const float*)d_in[9],  (const float*)d_in[10],
        (const float*)d_in[11], (const float*)d_in[12],
        (const float*)d_in[13], (const float*)d_in[14],
        (const float*)d_in[15], (const float*)d_in[16],
        (const float*)d_in[17], (const float*)d_in[18],
        (const float*)d_in[19], (const float*)d_in[20],
        (const float*)d_in[21], (const float*)d_in[22],
        (const float*)d_in[23], (const float*)d_in[24]);

    // stage -> constant bank (graph-capturable D2D memcpy node)
    void* foldAddr = nullptr;
    cudaGetSymbolAddress(&foldAddr, g_fold);
    cudaMemcpyToSymbolAsync(cc, foldAddr, sizeof(Consts), 0,
                            cudaMemcpyDeviceToDevice, 0);

    const int total = LN * HW;          // 327680
    const int threads = 256;
    const int blocks = (total + threads - 1) / threads;   // 1280
    disco_fused_kernel<<<blocks, threads>>>(x, (float*)d_out);
}